// round 11
// baseline (speedup 1.0000x reference)
#include <cuda_runtime.h>
#include <cuda_bf16.h>
#include <math.h>
#include <stdint.h>

#define NN   20000
#define NE   320000
#define DIN  128
#define HH   1024
#define HMID 256
#define DOUTC 10
#define EPSF 1e-5f

// ---------------- scratch (device globals) -----------------------------------
__device__ __align__(16) float g_buf1[(size_t)NN * HH];
__device__ __align__(16) float g_buf2[(size_t)NN * HH];
__device__ __align__(16) float g_mbuf[(size_t)NN * HMID];
__device__ __align__(16) __nv_bfloat16 g_ahi[(size_t)NN * HH];
__device__ __align__(16) __nv_bfloat16 g_alo[(size_t)NN * HH];
__device__ __align__(16) __nv_bfloat16 g_w1hi[(size_t)HH * DIN];
__device__ __align__(16) __nv_bfloat16 g_w1lo[(size_t)HH * DIN];
__device__ __align__(16) __nv_bfloat16 g_w2hi[(size_t)HH * HH];
__device__ __align__(16) __nv_bfloat16 g_w2lo[(size_t)HH * HH];
__device__ __align__(16) __nv_bfloat16 g_wl1hi[(size_t)HMID * HH];
__device__ __align__(16) __nv_bfloat16 g_wl1lo[(size_t)HMID * HH];
__device__ float g_deg[NN];
__device__ float g_dinv[NN];
__device__ int   g_cnt[NN];
__device__ int   g_fill[NN];
__device__ int   g_rowptr[NN + 1];
__device__ int   g_esrc[NE];
__device__ float g_ecoef[NE];
__device__ __align__(16) float g_colsum[HH];
__device__ __align__(16) float g_colsq[HH];
__device__ __align__(16) float g_bnA[HH];
__device__ __align__(16) float g_bnB[HH];
__device__ int   g_bsum[64];

__device__ __forceinline__ float* buf_ptr(int sel) {
    return sel == 1 ? g_buf1 : (sel == 2 ? g_buf2 : g_mbuf);
}
__device__ __forceinline__ __nv_bfloat16* wbuf_hi(int sel) {
    return sel == 1 ? g_w1hi : (sel == 2 ? g_w2hi : g_wl1hi);
}
__device__ __forceinline__ __nv_bfloat16* wbuf_lo(int sel) {
    return sel == 1 ? g_w1lo : (sel == 2 ? g_w2lo : g_wl1lo);
}

// ---------------- PTX helpers (sm_80-compatible only) -------------------------
__device__ __forceinline__ uint32_t smem_u32(const void* p) {
    uint32_t a;
    asm("{ .reg .u64 t; cvta.to.shared.u64 t, %1; cvt.u32.u64 %0, t; }" : "=r"(a) : "l"(p));
    return a;
}
__device__ __forceinline__ void cp_async16(uint32_t dst, const void* src, uint32_t srcsize) {
    asm volatile("cp.async.cg.shared.global [%0], [%1], 16, %2;"
                 :: "r"(dst), "l"(src), "r"(srcsize) : "memory");
}
__device__ __forceinline__ void cp_commit() {
    asm volatile("cp.async.commit_group;" ::: "memory");
}
template<int NG>
__device__ __forceinline__ void cp_wait() {
    asm volatile("cp.async.wait_group %0;" :: "n"(NG) : "memory");
}
__device__ __forceinline__ void ldm4(uint32_t& r0, uint32_t& r1, uint32_t& r2, uint32_t& r3,
                                     uint32_t addr) {
    asm volatile("ldmatrix.sync.aligned.m8n8.x4.shared.b16 {%0,%1,%2,%3}, [%4];"
                 : "=r"(r0), "=r"(r1), "=r"(r2), "=r"(r3) : "r"(addr));
}
__device__ __forceinline__ void mma16816(float* c, uint32_t a0, uint32_t a1, uint32_t a2,
                                         uint32_t a3, uint32_t b0, uint32_t b1) {
    asm volatile(
        "mma.sync.aligned.m16n8k16.row.col.f32.bf16.bf16.f32 "
        "{%0,%1,%2,%3},{%4,%5,%6,%7},{%8,%9},{%0,%1,%2,%3};"
        : "+f"(c[0]), "+f"(c[1]), "+f"(c[2]), "+f"(c[3])
        : "r"(a0), "r"(a1), "r"(a2), "r"(a3), "r"(b0), "r"(b1));
}
__device__ __forceinline__ uint32_t swz(uint32_t off) {
    return off ^ ((off >> 3) & 0x70);
}

// ---------------- weight transpose+split tile (shared helper) ------------------
__device__ __forceinline__ void wsplit_tile(const float* __restrict__ W, int K, int N,
                                            int k0, int n0,
                                            __nv_bfloat16* whi, __nv_bfloat16* wlo,
                                            float (*t)[33])
{
    const int tx = threadIdx.x & 31, ty = threadIdx.x >> 5;
    #pragma unroll
    for (int r = 0; r < 8; r++)
        t[ty + r * 8][tx] = W[(size_t)(k0 + ty + r * 8) * N + n0 + tx];
    __syncthreads();
    #pragma unroll
    for (int r = 0; r < 4; r++) {
        int n = ty + r * 8;
        float a0 = t[tx * 2][n], a1 = t[tx * 2 + 1][n];
        __nv_bfloat16 h0 = __float2bfloat16(a0), h1 = __float2bfloat16(a1);
        float l0f = a0 - __bfloat162float(h0), l1f = a1 - __bfloat162float(h1);
        __nv_bfloat162 hh; hh.x = h0; hh.y = h1;
        __nv_bfloat162 ll; ll.x = __float2bfloat16(l0f); ll.y = __float2bfloat16(l1f);
        size_t o = (size_t)(n0 + n) * K + k0 + tx * 2;
        *(__nv_bfloat162*)(whi + o) = hh;
        *(__nv_bfloat162*)(wlo + o) = ll;
    }
}

// ---------------- graph preprocessing -----------------------------------------
__global__ void init_k() {
    int i = blockIdx.x * blockDim.x + threadIdx.x;
    if (i < NN) { g_deg[i] = 1.0f; g_cnt[i] = 0; g_fill[i] = 0; }
    if (i < HH) { g_colsum[i] = 0.f; g_colsq[i] = 0.f; }
}
__global__ void count_k(const int* __restrict__ ei, const float* __restrict__ ew) {
    int e = blockIdx.x * blockDim.x + threadIdx.x;
    if (e >= NE) return;
    int d = ei[NE + e];
    atomicAdd(&g_deg[d], ew[e]);
    atomicAdd(&g_cnt[d], 1);
}
// scan1 also computes dinv (both depend only on count_k output)
__global__ void scan1_k() {
    __shared__ int sh[512];
    int i = blockIdx.x * 512 + threadIdx.x;
    if (i < NN) g_dinv[i] = rsqrtf(g_deg[i]);
    int v = (i < NN) ? g_cnt[i] : 0;
    sh[threadIdx.x] = v;
    __syncthreads();
    #pragma unroll
    for (int off = 1; off < 512; off <<= 1) {
        int t = 0;
        if (threadIdx.x >= off) t = sh[threadIdx.x - off];
        __syncthreads();
        sh[threadIdx.x] += t;
        __syncthreads();
    }
    if (i < NN) g_rowptr[i] = sh[threadIdx.x] - v;
    if (threadIdx.x == 511) g_bsum[blockIdx.x] = sh[511];
}
__global__ void scan2_k() {
    int acc = 0;
    for (int b = 0; b < 40; b++) { int t = g_bsum[b]; g_bsum[b] = acc; acc += t; }
}
__global__ void scan3_k() {
    int i = blockIdx.x * 512 + threadIdx.x;
    if (i < NN) g_rowptr[i] += g_bsum[blockIdx.x];
    if (i == 0) g_rowptr[NN] = NE;
}
__global__ void fill_k(const int* __restrict__ ei, const float* __restrict__ ew) {
    int e = blockIdx.x * blockDim.x + threadIdx.x;
    if (e >= NE) return;
    int s = ei[e];
    int d = ei[NE + e];
    int pos = g_rowptr[d] + atomicAdd(&g_fill[d], 1);
    g_esrc[pos]  = s;
    g_ecoef[pos] = g_dinv[s] * ew[e] * g_dinv[d];
}

// ---------------- layer-1: agg(x)->bf16 split, tail blocks split W1 ------------
#define AGGX_BLOCKS 2500
__global__ void __launch_bounds__(256)
aggx_w1_k(const float* __restrict__ x, const float* __restrict__ W1)
{
    __shared__ float t[64][33];
    if (blockIdx.x >= AGGX_BLOCKS) {
        int e = blockIdx.x - AGGX_BLOCKS;          // 0..63: W1 tiles
        wsplit_tile(W1, DIN, HH, (e >> 5) * 64, (e & 31) * 32, g_w1hi, g_w1lo, t);
        return;
    }
    const int node = blockIdx.x * 8 + (threadIdx.x >> 5);
    if (node >= NN) return;
    const int lane = threadIdx.x & 31;
    const float di = g_dinv[node];
    const float cself = di * di;

    float4 v = ((const float4*)(x + (size_t)node * DIN))[lane];
    float4 acc;
    acc.x = cself * v.x; acc.y = cself * v.y;
    acc.z = cself * v.z; acc.w = cself * v.w;

    const int beg = g_rowptr[node];
    const int end = g_rowptr[node + 1];
    for (int j = beg; j < end; j++) {
        int s = g_esrc[j];
        float c = g_ecoef[j];
        float4 u = ((const float4*)(x + (size_t)s * DIN))[lane];
        acc.x = fmaf(c, u.x, acc.x); acc.y = fmaf(c, u.y, acc.y);
        acc.z = fmaf(c, u.z, acc.z); acc.w = fmaf(c, u.w, acc.w);
    }
    float y[4] = {acc.x, acc.y, acc.z, acc.w};
    __nv_bfloat16 h[4], l[4];
    #pragma unroll
    for (int i = 0; i < 4; i++) {
        h[i] = __float2bfloat16(y[i]);
        l[i] = __float2bfloat16(y[i] - __bfloat162float(h[i]));
    }
    size_t e = (size_t)node * DIN + lane * 4;
    __nv_bfloat162 hh0; hh0.x = h[0]; hh0.y = h[1];
    __nv_bfloat162 hh1; hh1.x = h[2]; hh1.y = h[3];
    __nv_bfloat162 ll0; ll0.x = l[0]; ll0.y = l[1];
    __nv_bfloat162 ll1; ll1.x = l[2]; ll1.y = l[3];
    *(__nv_bfloat162*)(g_ahi + e)     = hh0;
    *(__nv_bfloat162*)(g_ahi + e + 2) = hh1;
    *(__nv_bfloat162*)(g_alo + e)     = ll0;
    *(__nv_bfloat162*)(g_alo + e + 2) = ll1;
}

// ---------------- mma.sync bf16 split GEMM: 256x128 tile, 2-stage --------------
// smem stage: Ahi 32K | Alo 32K | Bhi 16K | Blo 16K = 96 KB; 2 stages = 192 KB
// warps: 4 over M (64 rows), 2 over N (64 cols); acc[4][8][4]
template<int WSEL, int CSEL, int BIASRELU, int STATS, int EXTRA>
__global__ void __launch_bounds__(256)
tcmma_k(const float* __restrict__ bias,
        const float* __restrict__ Wx2, const float* __restrict__ Wxl1,
        int M, int N, int K)
{
    extern __shared__ char smem[];
    const int MROWS = (M + 255) / 256;
    if (EXTRA && (int)blockIdx.y >= MROWS) {
        int e = ((int)blockIdx.y - MROWS) * gridDim.x + blockIdx.x;  // 0..639
        float (*t)[33] = (float(*)[33])smem;
        if (e < 512)
            wsplit_tile(Wx2, HH, HH, (e >> 5) * 64, (e & 31) * 32, g_w2hi, g_w2lo, t);
        else {
            int e2 = e - 512;
            wsplit_tile(Wxl1, HH, HMID, (e2 >> 3) * 64, (e2 & 7) * 32, g_wl1hi, g_wl1lo, t);
        }
        return;
    }

    const uint32_t sbase = smem_u32(smem);
    const int tid = threadIdx.x;
    const int wid = tid >> 5;
    const int lane = tid & 31;
    const int warp_m = wid & 3;        // 4 warps over M, 64 rows each
    const int warp_n = wid >> 2;       // 2 warps over N, 64 cols each
    const int mbase = blockIdx.y * 256;
    const int nbase = blockIdx.x * 128;
    float* C = buf_ptr(CSEL);
    const __nv_bfloat16* whi = wbuf_hi(WSEL);
    const __nv_bfloat16* wlo = wbuf_lo(WSEL);

    const int NCH = K >> 6;
    const uint32_t STAGE = 98304u;

    auto load_chunk = [&](int c, int s) {
        uint32_t stb = sbase + (uint32_t)s * STAGE;
        #pragma unroll
        for (int j = 0; j < 8; j++) {              // A: 256 rows
            int q = tid + j * 256;
            int row = q >> 3, grp = q & 7;
            uint32_t sw = swz((uint32_t)(row << 7) + (grp << 4));
            int m = mbase + row;
            size_t gia = (size_t)m * K + (c << 6) + (grp << 3);
            uint32_t vs = (m < M) ? 16u : 0u;
            cp_async16(stb + sw,          g_ahi + gia, vs);
            cp_async16(stb + 32768 + sw,  g_alo + gia, vs);
        }
        #pragma unroll
        for (int j = 0; j < 4; j++) {              // B: 128 rows (N)
            int q = tid + j * 256;
            int row = q >> 3, grp = q & 7;
            uint32_t sw = swz((uint32_t)(row << 7) + (grp << 4));
            size_t gib = (size_t)(nbase + row) * K + (c << 6) + (grp << 3);
            cp_async16(stb + 65536 + sw,  whi + gib, 16u);
            cp_async16(stb + 81920 + sw,  wlo + gib, 16u);
        }
        cp_commit();
    };

    float acc[4][8][4];
    #pragma unroll
    for (int i = 0; i < 4; i++)
        #pragma unroll
        for (int j = 0; j < 8; j++)
            #pragma unroll
            for (int r = 0; r < 4; r++) acc[i][j][r] = 0.f;

    const int a_row  = (lane & 7) + ((lane >> 3) & 1) * 8;
    const int a_kblk = lane >> 4;
    const int b_row  = (lane & 7) + (lane >> 4) * 8;
    const int b_kblk = (lane >> 3) & 1;

    const uint32_t a_off0 = (uint32_t)(warp_m * 64 + a_row) * 128 + a_kblk * 16;
    const uint32_t b_off0 = (uint32_t)(warp_n * 64 + b_row) * 128 + b_kblk * 16;

    load_chunk(0, 0);

    for (int c = 0; c < NCH; c++) {
        const int s = c & 1;
        if (c + 1 < NCH) { load_chunk(c + 1, s ^ 1); cp_wait<1>(); }
        else             { cp_wait<0>(); }
        __syncthreads();

        const uint32_t stb = sbase + (uint32_t)s * STAGE;
        #pragma unroll
        for (int ks = 0; ks < 4; ks++) {
            const uint32_t k2 = (uint32_t)ks * 32;
            uint32_t bh[16], bl[16];
            #pragma unroll
            for (int nb = 0; nb < 4; nb++) {
                uint32_t boff = swz(b_off0 + (uint32_t)nb * 2048 + k2);
                ldm4(bh[nb * 4], bh[nb * 4 + 1], bh[nb * 4 + 2], bh[nb * 4 + 3],
                     stb + 65536 + boff);
                ldm4(bl[nb * 4], bl[nb * 4 + 1], bl[nb * 4 + 2], bl[nb * 4 + 3],
                     stb + 81920 + boff);
            }
            #pragma unroll
            for (int mm = 0; mm < 4; mm++) {
                uint32_t ah0, ah1, ah2, ah3, al0, al1, al2, al3;
                uint32_t aoff = swz(a_off0 + (uint32_t)mm * 2048 + k2);
                ldm4(ah0, ah1, ah2, ah3, stb + aoff);
                ldm4(al0, al1, al2, al3, stb + 32768 + aoff);
                #pragma unroll
                for (int nn = 0; nn < 8; nn++) {
                    int base = (nn >> 1) * 4 + (nn & 1) * 2;
                    uint32_t b0 = bh[base], b1 = bh[base + 1];
                    uint32_t c0 = bl[base], c1 = bl[base + 1];
                    mma16816(acc[mm][nn], ah0, ah1, ah2, ah3, b0, b1);
                    mma16816(acc[mm][nn], ah0, ah1, ah2, ah3, c0, c1);
                    mma16816(acc[mm][nn], al0, al1, al2, al3, b0, b1);
                }
            }
        }
        __syncthreads();
    }

    // ---- store C ----
    #pragma unroll
    for (int mm = 0; mm < 4; mm++) {
        int m0 = mbase + warp_m * 64 + mm * 16 + (lane >> 2);
        #pragma unroll
        for (int nn = 0; nn < 8; nn++) {
            int n0 = nbase + warp_n * 64 + nn * 8 + (lane & 3) * 2;
            float2 v0 = make_float2(acc[mm][nn][0], acc[mm][nn][1]);
            float2 v1 = make_float2(acc[mm][nn][2], acc[mm][nn][3]);
            if (BIASRELU) {
                v0.x = fmaxf(v0.x + bias[n0], 0.f);
                v0.y = fmaxf(v0.y + bias[n0 + 1], 0.f);
                v1.x = fmaxf(v1.x + bias[n0], 0.f);
                v1.y = fmaxf(v1.y + bias[n0 + 1], 0.f);
            }
            if (m0 < M)     *(float2*)(C + (size_t)m0 * N + n0) = v0;
            if (m0 + 8 < M) *(float2*)(C + (size_t)(m0 + 8) * N + n0) = v1;
        }
    }

    // ---- fused BN column stats (rows >= M contribute exact zeros) ----
    if (STATS) {
        float cs[16], cq[16];
        #pragma unroll
        for (int nn = 0; nn < 8; nn++) {
            float s0 = 0.f, s1 = 0.f, q0 = 0.f, q1 = 0.f;
            #pragma unroll
            for (int mm = 0; mm < 4; mm++) {
                float a0 = acc[mm][nn][0], a1 = acc[mm][nn][1];
                float a2 = acc[mm][nn][2], a3 = acc[mm][nn][3];
                s0 += a0 + a2;  s1 += a1 + a3;
                q0 += a0 * a0 + a2 * a2;  q1 += a1 * a1 + a3 * a3;
            }
            cs[nn * 2] = s0; cs[nn * 2 + 1] = s1;
            cq[nn * 2] = q0; cq[nn * 2 + 1] = q1;
        }
        #pragma unroll
        for (int o = 4; o < 32; o <<= 1) {
            #pragma unroll
            for (int i = 0; i < 16; i++) {
                cs[i] += __shfl_xor_sync(0xFFFFFFFFu, cs[i], o);
                cq[i] += __shfl_xor_sync(0xFFFFFFFFu, cq[i], o);
            }
        }
        if (lane < 4) {
            #pragma unroll
            for (int nn = 0; nn < 8; nn++) {
                int n0 = nbase + warp_n * 64 + nn * 8 + lane * 2;
                atomicAdd(&g_colsum[n0],     cs[nn * 2]);
                atomicAdd(&g_colsum[n0 + 1], cs[nn * 2 + 1]);
                atomicAdd(&g_colsq[n0],      cq[nn * 2]);
                atomicAdd(&g_colsq[n0 + 1],  cq[nn * 2 + 1]);
            }
        }
    }
}

// ---------------- layer-2: CSR gather aggregation + fused BN stats -------------
template<int INSEL, int OUTSEL>
__global__ void __launch_bounds__(256)
agg_stats_k()
{
    const float* hin = buf_ptr(INSEL);
    float* hout = buf_ptr(OUTSEL);
    const int t = threadIdx.x;
    const int n0 = blockIdx.x * 32;

    float s[4] = {0.f, 0.f, 0.f, 0.f};
    float q[4] = {0.f, 0.f, 0.f, 0.f};

    for (int ni = 0; ni < 32; ni++) {
        const int node = n0 + ni;
        const float di = g_dinv[node];
        const float cself = di * di;

        float4 v = ((const float4*)(hin + (size_t)node * HH))[t];
        float4 acc;
        acc.x = cself * v.x; acc.y = cself * v.y;
        acc.z = cself * v.z; acc.w = cself * v.w;

        const int beg = g_rowptr[node];
        const int end = g_rowptr[node + 1];
        for (int j = beg; j < end; j++) {
            int sidx = g_esrc[j];
            float c = g_ecoef[j];
            float4 u = ((const float4*)(hin + (size_t)sidx * HH))[t];
            acc.x = fmaf(c, u.x, acc.x); acc.y = fmaf(c, u.y, acc.y);
            acc.z = fmaf(c, u.z, acc.z); acc.w = fmaf(c, u.w, acc.w);
        }
        ((float4*)(hout + (size_t)node * HH))[t] = acc;

        s[0] += acc.x; s[1] += acc.y; s[2] += acc.z; s[3] += acc.w;
        q[0] += acc.x * acc.x; q[1] += acc.y * acc.y;
        q[2] += acc.z * acc.z; q[3] += acc.w * acc.w;
    }
    #pragma unroll
    for (int i = 0; i < 4; i++) {
        atomicAdd(&g_colsum[t * 4 + i], s[i]);
        atomicAdd(&g_colsq[t * 4 + i], q[i]);
    }
}

// ---------------- BatchNorm coefficient kernels --------------------------------
// reads stats, emits coefs, and RESETS stats for the next layer
__global__ void bnfinal_k(const float* __restrict__ g, const float* __restrict__ beta) {
    int c = blockIdx.x * blockDim.x + threadIdx.x;
    if (c >= HH) return;
    float mean = g_colsum[c] * (1.0f / NN);
    float var  = g_colsq[c] * (1.0f / NN) - mean * mean;
    float sc = g[c] * rsqrtf(var + EPSF);
    g_bnA[c] = sc;
    g_bnB[c] = beta[c] - mean * sc;
    g_colsum[c] = 0.f;
    g_colsq[c] = 0.f;
}
// BN+ReLU, output directly as hi/lo bf16 split (next GEMM's A operand)
template<int INSEL>
__global__ void __launch_bounds__(256)
bnapply_split_k() {
    const float* in = buf_ptr(INSEL);
    const int t = threadIdx.x;
    size_t idx4 = (size_t)blockIdx.x * 256 + t;
    float4 v = ((const float4*)in)[idx4];
    float4 a = ((const float4*)g_bnA)[t];
    float4 b = ((const float4*)g_bnB)[t];
    float y0 = fmaxf(fmaf(a.x, v.x, b.x), 0.f);
    float y1 = fmaxf(fmaf(a.y, v.y, b.y), 0.f);
    float y2 = fmaxf(fmaf(a.z, v.z, b.z), 0.f);
    float y3 = fmaxf(fmaf(a.w, v.w, b.w), 0.f);

    __nv_bfloat16 h0 = __float2bfloat16(y0), h1 = __float2bfloat16(y1);
    __nv_bfloat16 h2 = __float2bfloat16(y2), h3 = __float2bfloat16(y3);
    __nv_bfloat16 l0 = __float2bfloat16(y0 - __bfloat162float(h0));
    __nv_bfloat16 l1 = __float2bfloat16(y1 - __bfloat162float(h1));
    __nv_bfloat16 l2 = __float2bfloat16(y2 - __bfloat162float(h2));
    __nv_bfloat16 l3 = __float2bfloat16(y3 - __bfloat162float(h3));

    size_t e = idx4 * 4;
    __nv_bfloat162 hh0; hh0.x = h0; hh0.y = h1;
    __nv_bfloat162 hh1; hh1.x = h2; hh1.y = h3;
    __nv_bfloat162 ll0; ll0.x = l0; ll0.y = l1;
    __nv_bfloat162 ll1; ll1.x = l2; ll1.y = l3;
    *(__nv_bfloat162*)(g_ahi + e)     = hh0;
    *(__nv_bfloat162*)(g_ahi + e + 2) = hh1;
    *(__nv_bfloat162*)(g_alo + e)     = ll0;
    *(__nv_bfloat162*)(g_alo + e + 2) = ll1;
}

// ---------------- final 256->10 GEMM + log_softmax -----------------------------
__global__ void final_k(const float* __restrict__ Wl2,
                        const float* __restrict__ bl2, float* __restrict__ out)
{
    __shared__ float w[HMID * DOUTC];
    __shared__ float b[DOUTC];
    for (int i = threadIdx.x; i < HMID * DOUTC; i += blockDim.x) w[i] = Wl2[i];
    if (threadIdx.x < DOUTC) b[threadIdx.x] = bl2[threadIdx.x];
    __syncthreads();

    int r = blockIdx.x * blockDim.x + threadIdx.x;
    if (r >= NN) return;

    float acc[DOUTC];
    #pragma unroll
    for (int j = 0; j < DOUTC; j++) acc[j] = b[j];

    const float* mr = g_mbuf + (size_t)r * HMID;
    for (int k = 0; k < HMID; k += 4) {
        float4 v = *(const float4*)(mr + k);
        #pragma unroll
        for (int j = 0; j < DOUTC; j++) {
            acc[j] = fmaf(v.x, w[(k + 0) * DOUTC + j], acc[j]);
            acc[j] = fmaf(v.y, w[(k + 1) * DOUTC + j], acc[j]);
            acc[j] = fmaf(v.z, w[(k + 2) * DOUTC + j], acc[j]);
            acc[j] = fmaf(v.w, w[(k + 3) * DOUTC + j], acc[j]);
        }
    }
    float mx = acc[0];
    #pragma unroll
    for (int j = 1; j < DOUTC; j++) mx = fmaxf(mx, acc[j]);
    float s = 0.f;
    #pragma unroll
    for (int j = 0; j < DOUTC; j++) s += expf(acc[j] - mx);
    float lse = mx + logf(s);
    #pragma unroll
    for (int j = 0; j < DOUTC; j++) out[(size_t)r * DOUTC + j] = acc[j] - lse;
}

// ---------------- launch -------------------------------------------------------
extern "C" void kernel_launch(void* const* d_in, const int* in_sizes, int n_in,
                              void* d_out, int out_size)
{
    const float* x     = (const float*)d_in[0];
    const int*   ei    = (const int*)d_in[1];     // int32 (JAX x64 disabled)
    const float* ew    = (const float*)d_in[2];
    const float* W1    = (const float*)d_in[3];
    const float* g1    = (const float*)d_in[5];
    const float* beta1 = (const float*)d_in[6];
    const float* W2    = (const float*)d_in[7];
    const float* g2    = (const float*)d_in[9];
    const float* beta2 = (const float*)d_in[10];
    const float* Wl1   = (const float*)d_in[11];
    const float* bl1   = (const float*)d_in[12];
    const float* Wl2   = (const float*)d_in[13];
    const float* bl2   = (const float*)d_in[14];
    float* out = (float*)d_out;

    const int SMEMSZ = 2 * 98304;   // 192 KB, 2-stage 256x128 tile
    cudaFuncSetAttribute(tcmma_k<1, 1, 0, 1, 1>, cudaFuncAttributeMaxDynamicSharedMemorySize, SMEMSZ);
    cudaFuncSetAttribute(tcmma_k<2, 1, 0, 0, 0>, cudaFuncAttributeMaxDynamicSharedMemorySize, SMEMSZ);
    cudaFuncSetAttribute(tcmma_k<3, 3, 1, 0, 0>, cudaFuncAttributeMaxDynamicSharedMemorySize, SMEMSZ);

    // graph preprocessing: degrees + CSR build (dinv folded into scan1,
    // colsum/colsq zeroing folded into init)
    init_k<<<(NN + 255) / 256, 256>>>();
    count_k<<<(NE + 255) / 256, 256>>>(ei, ew);
    scan1_k<<<40, 512>>>();
    scan2_k<<<1, 1>>>();
    scan3_k<<<40, 512>>>();
    fill_k<<<(NE + 255) / 256, 256>>>(ei, ew);

    // ---- layer 1 ----  agg(x)->split (+W1 tail); GEMM1(+stats, +W2/Wl1 tail)
    aggx_w1_k<<<AGGX_BLOCKS + 64, 256>>>(x, W1);
    tcmma_k<1, 1, 0, 1, 1><<<dim3(8, 79 + 80), 256, SMEMSZ>>>(nullptr, W2, Wl1, NN, HH, DIN);
    bnfinal_k<<<4, 256>>>(g1, beta1);
    bnapply_split_k<1><<<NN, 256>>>();

    // ---- layer 2 ----  GEMM2 -> buf1; agg(+stats) -> buf2; bn coefs; BN->split
    tcmma_k<2, 1, 0, 0, 0><<<dim3(8, 79), 256, SMEMSZ>>>(nullptr, nullptr, nullptr, NN, HH, HH);
    agg_stats_k<1, 2><<<NN / 32, 256>>>();
    bnfinal_k<<<4, 256>>>(g2, beta2);
    bnapply_split_k<2><<<NN, 256>>>();

    // ---- MLP head ----
    tcmma_k<3, 3, 1, 0, 0><<<dim3(2, 79), 256, SMEMSZ>>>(bl1, nullptr, nullptr, NN, HMID, HH);
    final_k<<<(NN + 127) / 128, 128>>>(Wl2, bl2, out);
}

// round 12
// speedup vs baseline: 1.0678x; 1.0678x over previous
#include <cuda_runtime.h>
#include <cuda_bf16.h>
#include <math.h>
#include <stdint.h>

#define NN   20000
#define NE   320000
#define DIN  128
#define HH   1024
#define HMID 256
#define DOUTC 10
#define EPSF 1e-5f

// ---------------- scratch (device globals) -----------------------------------
__device__ __align__(16) float g_buf1[(size_t)NN * HH];
__device__ __align__(16) float g_buf2[(size_t)NN * HH];
__device__ __align__(16) float g_mbuf[(size_t)NN * HMID];
__device__ __align__(16) __nv_bfloat16 g_ahi[(size_t)NN * HH];
__device__ __align__(16) __nv_bfloat16 g_alo[(size_t)NN * HH];
__device__ __align__(16) __nv_bfloat16 g_w1hi[(size_t)HH * DIN];
__device__ __align__(16) __nv_bfloat16 g_w1lo[(size_t)HH * DIN];
__device__ __align__(16) __nv_bfloat16 g_w2hi[(size_t)HH * HH];
__device__ __align__(16) __nv_bfloat16 g_w2lo[(size_t)HH * HH];
__device__ __align__(16) __nv_bfloat16 g_wl1hi[(size_t)HMID * HH];
__device__ __align__(16) __nv_bfloat16 g_wl1lo[(size_t)HMID * HH];
__device__ float g_deg[NN];
__device__ float g_dinv[NN];
__device__ int   g_cnt[NN];
__device__ int   g_fill[NN];
__device__ int   g_rowptr[NN + 1];
__device__ int   g_esrc[NE];
__device__ float g_ecoef[NE];
__device__ __align__(16) float g_colsum[HH];
__device__ __align__(16) float g_colsq[HH];
__device__ __align__(16) float g_bnA[HH];
__device__ __align__(16) float g_bnB[HH];
__device__ int   g_bsum[64];

__device__ __forceinline__ float* buf_ptr(int sel) {
    return sel == 1 ? g_buf1 : (sel == 2 ? g_buf2 : g_mbuf);
}
__device__ __forceinline__ __nv_bfloat16* wbuf_hi(int sel) {
    return sel == 1 ? g_w1hi : (sel == 2 ? g_w2hi : g_wl1hi);
}
__device__ __forceinline__ __nv_bfloat16* wbuf_lo(int sel) {
    return sel == 1 ? g_w1lo : (sel == 2 ? g_w2lo : g_wl1lo);
}

// ---------------- PTX helpers (sm_80-compatible only) -------------------------
__device__ __forceinline__ uint32_t smem_u32(const void* p) {
    uint32_t a;
    asm("{ .reg .u64 t; cvta.to.shared.u64 t, %1; cvt.u32.u64 %0, t; }" : "=r"(a) : "l"(p));
    return a;
}
__device__ __forceinline__ void cp_async16(uint32_t dst, const void* src, uint32_t srcsize) {
    asm volatile("cp.async.cg.shared.global [%0], [%1], 16, %2;"
                 :: "r"(dst), "l"(src), "r"(srcsize) : "memory");
}
__device__ __forceinline__ void cp_commit() {
    asm volatile("cp.async.commit_group;" ::: "memory");
}
template<int NG>
__device__ __forceinline__ void cp_wait() {
    asm volatile("cp.async.wait_group %0;" :: "n"(NG) : "memory");
}
__device__ __forceinline__ void ldm4(uint32_t& r0, uint32_t& r1, uint32_t& r2, uint32_t& r3,
                                     uint32_t addr) {
    asm volatile("ldmatrix.sync.aligned.m8n8.x4.shared.b16 {%0,%1,%2,%3}, [%4];"
                 : "=r"(r0), "=r"(r1), "=r"(r2), "=r"(r3) : "r"(addr));
}
__device__ __forceinline__ void mma16816(float* c, uint32_t a0, uint32_t a1, uint32_t a2,
                                         uint32_t a3, uint32_t b0, uint32_t b1) {
    asm volatile(
        "mma.sync.aligned.m16n8k16.row.col.f32.bf16.bf16.f32 "
        "{%0,%1,%2,%3},{%4,%5,%6,%7},{%8,%9},{%0,%1,%2,%3};"
        : "+f"(c[0]), "+f"(c[1]), "+f"(c[2]), "+f"(c[3])
        : "r"(a0), "r"(a1), "r"(a2), "r"(a3), "r"(b0), "r"(b1));
}
__device__ __forceinline__ uint32_t swz(uint32_t off) {
    return off ^ ((off >> 3) & 0x70);
}

// ---------------- weight transpose+split tile (shared helper) ------------------
// W [K,N] row-major -> WT_hi/lo [N,K] bf16; tile 64(k) x 32(n); 256 threads
__device__ __forceinline__ void wsplit_tile(const float* __restrict__ W, int K, int N,
                                            int k0, int n0,
                                            __nv_bfloat16* whi, __nv_bfloat16* wlo,
                                            float (*t)[33])
{
    const int tx = threadIdx.x & 31, ty = threadIdx.x >> 5;   // ty 0..7
    #pragma unroll
    for (int r = 0; r < 8; r++)
        t[ty + r * 8][tx] = W[(size_t)(k0 + ty + r * 8) * N + n0 + tx];
    __syncthreads();
    #pragma unroll
    for (int r = 0; r < 4; r++) {
        int n = ty + r * 8;
        float a0 = t[tx * 2][n], a1 = t[tx * 2 + 1][n];
        __nv_bfloat16 h0 = __float2bfloat16(a0), h1 = __float2bfloat16(a1);
        float l0f = a0 - __bfloat162float(h0), l1f = a1 - __bfloat162float(h1);
        __nv_bfloat162 hh; hh.x = h0; hh.y = h1;
        __nv_bfloat162 ll; ll.x = __float2bfloat16(l0f); ll.y = __float2bfloat16(l1f);
        size_t o = (size_t)(n0 + n) * K + k0 + tx * 2;
        *(__nv_bfloat162*)(whi + o) = hh;
        *(__nv_bfloat162*)(wlo + o) = ll;
    }
}

// ---------------- graph preprocessing -----------------------------------------
__global__ void init_k() {
    int i = blockIdx.x * blockDim.x + threadIdx.x;
    if (i < NN) { g_deg[i] = 1.0f; g_cnt[i] = 0; g_fill[i] = 0; }
    if (i < HH) { g_colsum[i] = 0.f; g_colsq[i] = 0.f; }
}
__global__ void count_k(const int* __restrict__ ei, const float* __restrict__ ew) {
    int e = blockIdx.x * blockDim.x + threadIdx.x;
    if (e >= NE) return;
    int d = ei[NE + e];
    atomicAdd(&g_deg[d], ew[e]);
    atomicAdd(&g_cnt[d], 1);
}
// scan1 also computes dinv (both depend only on count_k output)
__global__ void scan1_k() {
    __shared__ int sh[512];
    int i = blockIdx.x * 512 + threadIdx.x;
    if (i < NN) g_dinv[i] = rsqrtf(g_deg[i]);
    int v = (i < NN) ? g_cnt[i] : 0;
    sh[threadIdx.x] = v;
    __syncthreads();
    #pragma unroll
    for (int off = 1; off < 512; off <<= 1) {
        int t = 0;
        if (threadIdx.x >= off) t = sh[threadIdx.x - off];
        __syncthreads();
        sh[threadIdx.x] += t;
        __syncthreads();
    }
    if (i < NN) g_rowptr[i] = sh[threadIdx.x] - v;
    if (threadIdx.x == 511) g_bsum[blockIdx.x] = sh[511];
}
// scan3 computes its own block-offset prefix (<=40 adds) — scan2 eliminated
__global__ void scan3_k() {
    __shared__ int soff;
    if (threadIdx.x == 0) {
        int acc = 0;
        for (int b = 0; b < (int)blockIdx.x; b++) acc += g_bsum[b];
        soff = acc;
    }
    __syncthreads();
    int i = blockIdx.x * 512 + threadIdx.x;
    if (i < NN) g_rowptr[i] += soff;
    if (i == 0) g_rowptr[NN] = NE;
}
__global__ void fill_k(const int* __restrict__ ei, const float* __restrict__ ew) {
    int e = blockIdx.x * blockDim.x + threadIdx.x;
    if (e >= NE) return;
    int s = ei[e];
    int d = ei[NE + e];
    int pos = g_rowptr[d] + atomicAdd(&g_fill[d], 1);
    g_esrc[pos]  = s;
    g_ecoef[pos] = g_dinv[s] * ew[e] * g_dinv[d];
}

// ---------------- layer-1: agg(x)->bf16 split, tail blocks split W1 ------------
#define AGGX_BLOCKS 2500
__global__ void __launch_bounds__(256)
aggx_w1_k(const float* __restrict__ x, const float* __restrict__ W1)
{
    __shared__ float t[64][33];
    if (blockIdx.x >= AGGX_BLOCKS) {
        int e = blockIdx.x - AGGX_BLOCKS;          // 0..63: W1 tiles
        wsplit_tile(W1, DIN, HH, (e >> 5) * 64, (e & 31) * 32, g_w1hi, g_w1lo, t);
        return;
    }
    const int node = blockIdx.x * 8 + (threadIdx.x >> 5);
    if (node >= NN) return;
    const int lane = threadIdx.x & 31;
    const float di = g_dinv[node];
    const float cself = di * di;

    float4 v = ((const float4*)(x + (size_t)node * DIN))[lane];
    float4 acc;
    acc.x = cself * v.x; acc.y = cself * v.y;
    acc.z = cself * v.z; acc.w = cself * v.w;

    const int beg = g_rowptr[node];
    const int end = g_rowptr[node + 1];
    for (int j = beg; j < end; j++) {
        int s = g_esrc[j];
        float c = g_ecoef[j];
        float4 u = ((const float4*)(x + (size_t)s * DIN))[lane];
        acc.x = fmaf(c, u.x, acc.x); acc.y = fmaf(c, u.y, acc.y);
        acc.z = fmaf(c, u.z, acc.z); acc.w = fmaf(c, u.w, acc.w);
    }
    float y[4] = {acc.x, acc.y, acc.z, acc.w};
    __nv_bfloat16 h[4], l[4];
    #pragma unroll
    for (int i = 0; i < 4; i++) {
        h[i] = __float2bfloat16(y[i]);
        l[i] = __float2bfloat16(y[i] - __bfloat162float(h[i]));
    }
    size_t e = (size_t)node * DIN + lane * 4;
    __nv_bfloat162 hh0; hh0.x = h[0]; hh0.y = h[1];
    __nv_bfloat162 hh1; hh1.x = h[2]; hh1.y = h[3];
    __nv_bfloat162 ll0; ll0.x = l[0]; ll0.y = l[1];
    __nv_bfloat162 ll1; ll1.x = l[2]; ll1.y = l[3];
    *(__nv_bfloat162*)(g_ahi + e)     = hh0;
    *(__nv_bfloat162*)(g_ahi + e + 2) = hh1;
    *(__nv_bfloat162*)(g_alo + e)     = ll0;
    *(__nv_bfloat162*)(g_alo + e + 2) = ll1;
}

// ---------------- mma.sync bf16 split GEMM (128x128 tile, 3-stage) -------------
// WSEL selects weight buffers; STATS fuses BN column stats; EXTRA appends
// W2/Wl1 transpose-split work as tail grid rows (scheduled last -> drain fill).
template<int WSEL, int CSEL, int BIASRELU, int STATS, int EXTRA>
__global__ void __launch_bounds__(256)
tcmma_k(const float* __restrict__ bias,
        const float* __restrict__ Wx2, const float* __restrict__ Wxl1,
        int M, int N, int K)
{
    extern __shared__ char smem[];
    const int MROWS = (M + 127) / 128;
    if (EXTRA && (int)blockIdx.y >= MROWS) {
        int e = ((int)blockIdx.y - MROWS) * gridDim.x + blockIdx.x;  // 0..639
        float (*t)[33] = (float(*)[33])smem;
        if (e < 512)
            wsplit_tile(Wx2, HH, HH, (e >> 5) * 64, (e & 31) * 32, g_w2hi, g_w2lo, t);
        else {
            int e2 = e - 512;                                        // 0..127
            wsplit_tile(Wxl1, HH, HMID, (e2 >> 3) * 64, (e2 & 7) * 32, g_wl1hi, g_wl1lo, t);
        }
        return;
    }

    const uint32_t sbase = smem_u32(smem);
    const int tid = threadIdx.x;
    const int wid = tid >> 5;
    const int lane = tid & 31;
    const int warp_m = wid & 1;
    const int warp_n = wid >> 1;
    const int mbase = blockIdx.y * 128;
    const int nbase = blockIdx.x * 128;
    float* C = buf_ptr(CSEL);
    const __nv_bfloat16* whi = wbuf_hi(WSEL);
    const __nv_bfloat16* wlo = wbuf_lo(WSEL);

    const int NCH = K >> 6;

    auto load_chunk = [&](int c, int s) {
        uint32_t stb = sbase + (uint32_t)s * 65536u;
        #pragma unroll
        for (int j = 0; j < 4; j++) {
            int q = tid + j * 256;
            int row = q >> 3, grp = q & 7;
            uint32_t sw = swz((uint32_t)(row << 7) + (grp << 4));
            int m = mbase + row;
            size_t gia = (size_t)m * K + (c << 6) + (grp << 3);
            uint32_t vs = (m < M) ? 16u : 0u;
            cp_async16(stb + sw,          g_ahi + gia, vs);
            cp_async16(stb + 16384 + sw,  g_alo + gia, vs);
            size_t gib = (size_t)(nbase + row) * K + (c << 6) + (grp << 3);
            cp_async16(stb + 32768 + sw,  whi + gib, 16u);
            cp_async16(stb + 49152 + sw,  wlo + gib, 16u);
        }
        cp_commit();
    };

    float acc[4][4][4];
    #pragma unroll
    for (int i = 0; i < 4; i++)
        #pragma unroll
        for (int j = 0; j < 4; j++)
            #pragma unroll
            for (int r = 0; r < 4; r++) acc[i][j][r] = 0.f;

    const int a_row  = (lane & 7) + ((lane >> 3) & 1) * 8;
    const int a_kblk = lane >> 4;
    const int b_row  = (lane & 7) + (lane >> 4) * 8;
    const int b_kblk = (lane >> 3) & 1;

    const uint32_t a_off0 = (uint32_t)(warp_m * 64 + a_row) * 128 + a_kblk * 16;
    const uint32_t b_off0 = (uint32_t)(warp_n * 32 + b_row) * 128 + b_kblk * 16;

    load_chunk(0, 0);
    if (NCH > 1) load_chunk(1, 1);

    for (int c = 0; c < NCH; c++) {
        const int s = c % 3;
        if (c + 2 < NCH)      { load_chunk(c + 2, (c + 2) % 3); cp_wait<2>(); }
        else if (c + 1 < NCH) { cp_wait<1>(); }
        else                  { cp_wait<0>(); }
        __syncthreads();

        const uint32_t stb = sbase + (uint32_t)s * 65536u;
        #pragma unroll
        for (int ks = 0; ks < 4; ks++) {
            const uint32_t k2 = (uint32_t)(ks * 16) * 2;
            uint32_t bh[8], bl[8];
            ldm4(bh[0], bh[1], bh[2], bh[3], stb + 32768 + swz(b_off0 + k2));
            ldm4(bh[4], bh[5], bh[6], bh[7], stb + 32768 + swz(b_off0 + 2048 + k2));
            ldm4(bl[0], bl[1], bl[2], bl[3], stb + 49152 + swz(b_off0 + k2));
            ldm4(bl[4], bl[5], bl[6], bl[7], stb + 49152 + swz(b_off0 + 2048 + k2));
            #pragma unroll
            for (int mm = 0; mm < 4; mm++) {
                uint32_t ah0, ah1, ah2, ah3, al0, al1, al2, al3;
                uint32_t aoff = swz(a_off0 + (uint32_t)mm * 2048 + k2);
                ldm4(ah0, ah1, ah2, ah3, stb + aoff);
                ldm4(al0, al1, al2, al3, stb + 16384 + aoff);
                #pragma unroll
                for (int nn = 0; nn < 4; nn++) {
                    uint32_t b0 = bh[nn * 2], b1 = bh[nn * 2 + 1];
                    uint32_t c0 = bl[nn * 2], c1 = bl[nn * 2 + 1];
                    mma16816(acc[mm][nn], ah0, ah1, ah2, ah3, b0, b1);
                    mma16816(acc[mm][nn], ah0, ah1, ah2, ah3, c0, c1);
                    mma16816(acc[mm][nn], al0, al1, al2, al3, b0, b1);
                }
            }
        }
        __syncthreads();
    }

    // ---- store C ----
    #pragma unroll
    for (int mm = 0; mm < 4; mm++) {
        int m0 = mbase + warp_m * 64 + mm * 16 + (lane >> 2);
        #pragma unroll
        for (int nn = 0; nn < 4; nn++) {
            int n0 = nbase + warp_n * 32 + nn * 8 + (lane & 3) * 2;
            float2 v0 = make_float2(acc[mm][nn][0], acc[mm][nn][1]);
            float2 v1 = make_float2(acc[mm][nn][2], acc[mm][nn][3]);
            if (BIASRELU) {
                v0.x = fmaxf(v0.x + bias[n0], 0.f);
                v0.y = fmaxf(v0.y + bias[n0 + 1], 0.f);
                v1.x = fmaxf(v1.x + bias[n0], 0.f);
                v1.y = fmaxf(v1.y + bias[n0 + 1], 0.f);
            }
            if (m0 < M)     *(float2*)(C + (size_t)m0 * N + n0) = v0;
            if (m0 + 8 < M) *(float2*)(C + (size_t)(m0 + 8) * N + n0) = v1;
        }
    }

    // ---- fused BN column stats (rows >= M contribute exact zeros) ----
    if (STATS) {
        float cs[8], cq[8];
        #pragma unroll
        for (int nn = 0; nn < 4; nn++) {
            float s0 = 0.f, s1 = 0.f, q0 = 0.f, q1 = 0.f;
            #pragma unroll
            for (int mm = 0; mm < 4; mm++) {
                float a0 = acc[mm][nn][0], a1 = acc[mm][nn][1];
                float a2 = acc[mm][nn][2], a3 = acc[mm][nn][3];
                s0 += a0 + a2;  s1 += a1 + a3;
                q0 += a0 * a0 + a2 * a2;  q1 += a1 * a1 + a3 * a3;
            }
            cs[nn * 2] = s0; cs[nn * 2 + 1] = s1;
            cq[nn * 2] = q0; cq[nn * 2 + 1] = q1;
        }
        #pragma unroll
        for (int o = 4; o < 32; o <<= 1) {
            #pragma unroll
            for (int i = 0; i < 8; i++) {
                cs[i] += __shfl_xor_sync(0xFFFFFFFFu, cs[i], o);
                cq[i] += __shfl_xor_sync(0xFFFFFFFFu, cq[i], o);
            }
        }
        if (lane < 4) {
            #pragma unroll
            for (int nn = 0; nn < 4; nn++) {
                int n0 = nbase + warp_n * 32 + nn * 8 + lane * 2;
                atomicAdd(&g_colsum[n0],     cs[nn * 2]);
                atomicAdd(&g_colsum[n0 + 1], cs[nn * 2 + 1]);
                atomicAdd(&g_colsq[n0],      cq[nn * 2]);
                atomicAdd(&g_colsq[n0 + 1],  cq[nn * 2 + 1]);
            }
        }
    }
}

// ---------------- layer-2: CSR gather aggregation + fused BN stats -------------
template<int INSEL, int OUTSEL>
__global__ void __launch_bounds__(256)
agg_stats_k()
{
    const float* hin = buf_ptr(INSEL);
    float* hout = buf_ptr(OUTSEL);
    const int t = threadIdx.x;
    const int n0 = blockIdx.x * 32;

    float s[4] = {0.f, 0.f, 0.f, 0.f};
    float q[4] = {0.f, 0.f, 0.f, 0.f};

    for (int ni = 0; ni < 32; ni++) {
        const int node = n0 + ni;
        const float di = g_dinv[node];
        const float cself = di * di;

        float4 v = ((const float4*)(hin + (size_t)node * HH))[t];
        float4 acc;
        acc.x = cself * v.x; acc.y = cself * v.y;
        acc.z = cself * v.z; acc.w = cself * v.w;

        const int beg = g_rowptr[node];
        const int end = g_rowptr[node + 1];
        for (int j = beg; j < end; j++) {
            int sidx = g_esrc[j];
            float c = g_ecoef[j];
            float4 u = ((const float4*)(hin + (size_t)sidx * HH))[t];
            acc.x = fmaf(c, u.x, acc.x); acc.y = fmaf(c, u.y, acc.y);
            acc.z = fmaf(c, u.z, acc.z); acc.w = fmaf(c, u.w, acc.w);
        }
        ((float4*)(hout + (size_t)node * HH))[t] = acc;

        s[0] += acc.x; s[1] += acc.y; s[2] += acc.z; s[3] += acc.w;
        q[0] += acc.x * acc.x; q[1] += acc.y * acc.y;
        q[2] += acc.z * acc.z; q[3] += acc.w * acc.w;
    }
    #pragma unroll
    for (int i = 0; i < 4; i++) {
        atomicAdd(&g_colsum[t * 4 + i], s[i]);
        atomicAdd(&g_colsq[t * 4 + i], q[i]);
    }
}

// ---------------- BatchNorm coefficient kernels --------------------------------
// reads stats, emits coefs, and RESETS stats for the next layer
__global__ void bnfinal_k(const float* __restrict__ g, const float* __restrict__ beta) {
    int c = blockIdx.x * blockDim.x + threadIdx.x;
    if (c >= HH) return;
    float mean = g_colsum[c] * (1.0f / NN);
    float var  = g_colsq[c] * (1.0f / NN) - mean * mean;
    float sc = g[c] * rsqrtf(var + EPSF);
    g_bnA[c] = sc;
    g_bnB[c] = beta[c] - mean * sc;
    g_colsum[c] = 0.f;
    g_colsq[c] = 0.f;
}
// BN+ReLU, output directly as hi/lo bf16 split (next GEMM's A operand)
template<int INSEL>
__global__ void __launch_bounds__(256)
bnapply_split_k() {
    const float* in = buf_ptr(INSEL);
    const int t = threadIdx.x;
    size_t idx4 = (size_t)blockIdx.x * 256 + t;
    float4 v = ((const float4*)in)[idx4];
    float4 a = ((const float4*)g_bnA)[t];
    float4 b = ((const float4*)g_bnB)[t];
    float y0 = fmaxf(fmaf(a.x, v.x, b.x), 0.f);
    float y1 = fmaxf(fmaf(a.y, v.y, b.y), 0.f);
    float y2 = fmaxf(fmaf(a.z, v.z, b.z), 0.f);
    float y3 = fmaxf(fmaf(a.w, v.w, b.w), 0.f);

    __nv_bfloat16 h0 = __float2bfloat16(y0), h1 = __float2bfloat16(y1);
    __nv_bfloat16 h2 = __float2bfloat16(y2), h3 = __float2bfloat16(y3);
    __nv_bfloat16 l0 = __float2bfloat16(y0 - __bfloat162float(h0));
    __nv_bfloat16 l1 = __float2bfloat16(y1 - __bfloat162float(h1));
    __nv_bfloat16 l2 = __float2bfloat16(y2 - __bfloat162float(h2));
    __nv_bfloat16 l3 = __float2bfloat16(y3 - __bfloat162float(h3));

    size_t e = idx4 * 4;
    __nv_bfloat162 hh0; hh0.x = h0; hh0.y = h1;
    __nv_bfloat162 hh1; hh1.x = h2; hh1.y = h3;
    __nv_bfloat162 ll0; ll0.x = l0; ll0.y = l1;
    __nv_bfloat162 ll1; ll1.x = l2; ll1.y = l3;
    *(__nv_bfloat162*)(g_ahi + e)     = hh0;
    *(__nv_bfloat162*)(g_ahi + e + 2) = hh1;
    *(__nv_bfloat162*)(g_alo + e)     = ll0;
    *(__nv_bfloat162*)(g_alo + e + 2) = ll1;
}

// ---------------- final 256->10 GEMM + log_softmax -----------------------------
__global__ void final_k(const float* __restrict__ Wl2,
                        const float* __restrict__ bl2, float* __restrict__ out)
{
    __shared__ float w[HMID * DOUTC];
    __shared__ float b[DOUTC];
    for (int i = threadIdx.x; i < HMID * DOUTC; i += blockDim.x) w[i] = Wl2[i];
    if (threadIdx.x < DOUTC) b[threadIdx.x] = bl2[threadIdx.x];
    __syncthreads();

    int r = blockIdx.x * blockDim.x + threadIdx.x;
    if (r >= NN) return;

    float acc[DOUTC];
    #pragma unroll
    for (int j = 0; j < DOUTC; j++) acc[j] = b[j];

    const float* mr = g_mbuf + (size_t)r * HMID;
    for (int k = 0; k < HMID; k += 4) {
        float4 v = *(const float4*)(mr + k);
        #pragma unroll
        for (int j = 0; j < DOUTC; j++) {
            acc[j] = fmaf(v.x, w[(k + 0) * DOUTC + j], acc[j]);
            acc[j] = fmaf(v.y, w[(k + 1) * DOUTC + j], acc[j]);
            acc[j] = fmaf(v.z, w[(k + 2) * DOUTC + j], acc[j]);
            acc[j] = fmaf(v.w, w[(k + 3) * DOUTC + j], acc[j]);
        }
    }
    float mx = acc[0];
    #pragma unroll
    for (int j = 1; j < DOUTC; j++) mx = fmaxf(mx, acc[j]);
    float s = 0.f;
    #pragma unroll
    for (int j = 0; j < DOUTC; j++) s += expf(acc[j] - mx);
    float lse = mx + logf(s);
    #pragma unroll
    for (int j = 0; j < DOUTC; j++) out[(size_t)r * DOUTC + j] = acc[j] - lse;
}

// ---------------- launch -------------------------------------------------------
extern "C" void kernel_launch(void* const* d_in, const int* in_sizes, int n_in,
                              void* d_out, int out_size)
{
    const float* x     = (const float*)d_in[0];
    const int*   ei    = (const int*)d_in[1];     // int32 (JAX x64 disabled)
    const float* ew    = (const float*)d_in[2];
    const float* W1    = (const float*)d_in[3];
    const float* g1    = (const float*)d_in[5];
    const float* beta1 = (const float*)d_in[6];
    const float* W2    = (const float*)d_in[7];
    const float* g2    = (const float*)d_in[9];
    const float* beta2 = (const float*)d_in[10];
    const float* Wl1   = (const float*)d_in[11];
    const float* bl1   = (const float*)d_in[12];
    const float* Wl2   = (const float*)d_in[13];
    const float* bl2   = (const float*)d_in[14];
    float* out = (float*)d_out;

    const int SMEMSZ = 3 * 65536;   // 192 KB, 3-stage
    cudaFuncSetAttribute(tcmma_k<1, 1, 0, 1, 1>, cudaFuncAttributeMaxDynamicSharedMemorySize, SMEMSZ);
    cudaFuncSetAttribute(tcmma_k<2, 1, 0, 0, 0>, cudaFuncAttributeMaxDynamicSharedMemorySize, SMEMSZ);
    cudaFuncSetAttribute(tcmma_k<3, 3, 1, 0, 0>, cudaFuncAttributeMaxDynamicSharedMemorySize, SMEMSZ);

    // graph preprocessing: degrees + CSR build (dinv folded into scan1,
    // zerobn folded into init, scan2 folded into scan3)
    init_k<<<(NN + 255) / 256, 256>>>();
    count_k<<<(NE + 255) / 256, 256>>>(ei, ew);
    scan1_k<<<40, 512>>>();
    scan3_k<<<40, 512>>>();
    fill_k<<<(NE + 255) / 256, 256>>>(ei, ew);

    // ---- layer 1 ----  agg(x)->split (+W1 tail); GEMM1(+stats, +W2/Wl1 tail)
    aggx_w1_k<<<AGGX_BLOCKS + 64, 256>>>(x, W1);
    tcmma_k<1, 1, 0, 1, 1><<<dim3(8, 157 + 80), 256, SMEMSZ>>>(nullptr, W2, Wl1, NN, HH, DIN);
    bnfinal_k<<<4, 256>>>(g1, beta1);
    bnapply_split_k<1><<<NN, 256>>>();

    // ---- layer 2 ----  GEMM2 -> buf1; agg(+stats) -> buf2; bn coefs; BN->split
    tcmma_k<2, 1, 0, 0, 0><<<dim3(8, 157), 256, SMEMSZ>>>(nullptr, nullptr, nullptr, NN, HH, HH);
    agg_stats_k<1, 2><<<NN / 32, 256>>>();
    bnfinal_k<<<4, 256>>>(g2, beta2);
    bnapply_split_k<2><<<NN, 256>>>();

    // ---- MLP head ----
    tcmma_k<3, 3, 1, 0, 0><<<dim3(2, 157), 256, SMEMSZ>>>(bl1, nullptr, nullptr, NN, HMID, HH);
    final_k<<<(NN + 127) / 128, 128>>>(Wl2, bl2, out);
}